// round 1
// baseline (speedup 1.0000x reference)
#include <cuda_runtime.h>
#include <math.h>

// Problem constants
#define B_    8
#define KTOK  512
#define C_    256
#define HEADS 8
#define DH    32
#define NS    64
#define FF_   1024
#define NT    (B_*KTOK)   // 4096 tokens

// ---------------- scratch (device globals; no allocation allowed) ----------
__device__ float d_qp [NT*C_];          //  4 MB  q projection
__device__ float d_qk [NT*HEADS*C_];    // 32 MB  per-token per-head key-coef
__device__ float d_g  [NT*HEADS*C_];    // 32 MB  attention-weighted feats
__device__ float d_ctx[NT*C_];          //  4 MB
__device__ float d_y  [NT*C_];          //  4 MB
__device__ float d_x  [NT*C_];          //  4 MB
__device__ float d_h1 [NT*FF_];         // 16 MB

__device__ __forceinline__ float gelu_tanh(float x) {
    float x3 = x*x*x;
    return 0.5f*x*(1.f + tanhf(0.7978845608028654f*(x + 0.044715f*x3)));
}

// ---------------- generic tiled SIMT GEMM: C = A[M,K]@B[K,N] ---------------
// 64x64 tile, BK=16, 256 threads, 4x4 register micro-tile.
template<bool BIAS, bool RES, bool GELU>
__global__ void gemm64(const float* __restrict__ A, const float* __restrict__ Bm,
                       const float* __restrict__ bias, const float* __restrict__ res,
                       float* __restrict__ Cm, int M, int N, int K)
{
    __shared__ float As[16*68];   // [k][m], padded stride 68 (16B-aligned rows)
    __shared__ float Bs[16*68];   // [k][n]
    const int tid = threadIdx.x;
    const int tx = tid & 15, ty = tid >> 4;
    const int m0 = blockIdx.y * 64, n0 = blockIdx.x * 64;

    const int mA  = tid >> 2;          // 0..63
    const int kqA = (tid & 3) * 4;     // 0,4,8,12
    const int kB  = tid >> 4;          // 0..15
    const int nqB = (tid & 15) * 4;    // 0..60

    float acc[4][4] = {};

    for (int kt = 0; kt < K; kt += 16) {
        float4 a4 = *(const float4*)&A[(size_t)(m0 + mA)*K + kt + kqA];
        float4 b4 = *(const float4*)&Bm[(size_t)(kt + kB)*N + n0 + nqB];
        As[(kqA+0)*68 + mA] = a4.x;
        As[(kqA+1)*68 + mA] = a4.y;
        As[(kqA+2)*68 + mA] = a4.z;
        As[(kqA+3)*68 + mA] = a4.w;
        *(float4*)&Bs[kB*68 + nqB] = b4;
        __syncthreads();
        #pragma unroll
        for (int kk = 0; kk < 16; kk++) {
            float4 av = *(const float4*)&As[kk*68 + ty*4];
            float4 bv = *(const float4*)&Bs[kk*68 + tx*4];
            float am[4] = {av.x, av.y, av.z, av.w};
            float bn[4] = {bv.x, bv.y, bv.z, bv.w};
            #pragma unroll
            for (int i = 0; i < 4; i++)
                #pragma unroll
                for (int j = 0; j < 4; j++)
                    acc[i][j] += am[i]*bn[j];
        }
        __syncthreads();
    }

    #pragma unroll
    for (int i = 0; i < 4; i++) {
        int row = m0 + ty*4 + i;
        #pragma unroll
        for (int j = 0; j < 4; j++) {
            int col = n0 + tx*4 + j;
            float v = acc[i][j];
            if (BIAS) v += bias[col];
            if (RES)  v += res[(size_t)row*N + col];
            if (GELU) v = gelu_tanh(v);
            Cm[(size_t)row*N + col] = v;
        }
    }
}

// -------- qk_coef[bk,h,c] = (1/sqrt(32)) * sum_d qp[bk,h*32+d]*Wk[c,h*32+d] --
// grid (NT/64, HEADS), 256 threads. Thread t owns column c=t for 64 tokens.
__global__ void qk_kernel(const float* __restrict__ qp, const float* __restrict__ Wk,
                          float* __restrict__ qk)
{
    __shared__ float wks[32*257];  // [d][c], pad 257 -> conflict-free both ways
    __shared__ float qps[64*33];   // [r][d]
    const int tid = threadIdx.x;
    const int h   = blockIdx.y;
    const int bk0 = blockIdx.x * 64;

    #pragma unroll
    for (int j = 0; j < 32; j++) {
        int i = tid + 256*j;        // i = c*32 + d
        int c = i >> 5, d = i & 31;
        wks[d*257 + c] = Wk[c*C_ + h*DH + d];
    }
    #pragma unroll
    for (int j = 0; j < 8; j++) {
        int i = tid + 256*j;        // i = r*32 + d
        int r = i >> 5, d = i & 31;
        qps[r*33 + d] = qp[(size_t)(bk0 + r)*C_ + h*DH + d];
    }
    __syncthreads();

    float wreg[32];
    #pragma unroll
    for (int d = 0; d < 32; d++) wreg[d] = wks[d*257 + tid];

    const float scale = 0.17677669529663687f;  // 1/sqrt(32)
    for (int r = 0; r < 64; r++) {
        float acc = 0.f;
        #pragma unroll
        for (int d = 0; d < 32; d++) acc += qps[r*33 + d]*wreg[d];
        qk[((size_t)(bk0 + r)*HEADS + h)*C_ + tid] = acc*scale;
    }
}

// ---- bilinear tap of the 9x9 rel-pos table (align_corners, zeros padding) --
__device__ __forceinline__ float bil_corner(const float* __restrict__ th,
                                            int yi, int xi, float w)
{
    if (xi < 0 || xi > 8 || yi < 0 || yi > 8) return 0.f;
    return th[yi*9 + xi]*w;
}

// ---------------- fused local attention: one CTA per token -----------------
// scores = qk_coef . feats + grid_sample(bias); softmax over n;
// g[h,c] = sum_n attn[h,n]*feats[c,n]   -> written to d_g
__global__ void attn_kernel(const float* __restrict__ lf,   const float* __restrict__ spat,
                            const float* __restrict__ table, const float* __restrict__ qk,
                            float* __restrict__ gout)
{
    extern __shared__ float sm[];
    float* feats = sm;                // [256][65]  (pad 65: conflict-free both axes)
    float* qks   = feats + 256*65;    // [8][256]
    float* tab   = qks + 2048;        // 648 (pad 656)
    float* sc    = tab + 656;         // [8][64]
    float* sp    = sc  + 512;         // [64][2]

    const int tid = threadIdx.x;
    const int bk  = blockIdx.x;
    const int b   = bk >> 9, k = bk & 511;

    {
        const float4* q4 = (const float4*)(qk + (size_t)bk*2048);
        float4* s4 = (float4*)qks;
        s4[tid]       = q4[tid];
        s4[tid + 256] = q4[tid + 256];
    }
    if (tid < 128) sp[tid] = spat[(size_t)bk*128 + tid];
    for (int j = tid; j < 648; j += 256) tab[j] = table[j];

    // feats[c][n] <- local_feat[b, c, k, n]
    const float* lfb = lf + (size_t)b*(C_*KTOK*NS) + (size_t)k*NS;
    {
        const int v = tid & 15, cg = tid >> 4;
        #pragma unroll
        for (int rr = 0; rr < 16; rr++) {
            int c = rr*16 + cg;
            float4 f = *(const float4*)(lfb + (size_t)c*(KTOK*NS) + v*4);
            float* dst = &feats[c*65 + v*4];
            dst[0] = f.x; dst[1] = f.y; dst[2] = f.z; dst[3] = f.w;
        }
    }
    __syncthreads();

    // scores + bias  (512 (h,n) pairs, 2 per thread)
    #pragma unroll
    for (int pp = 0; pp < 2; pp++) {
        int p = tid + pp*256;
        int h = p >> 6, n = p & 63;
        const float* qrow = &qks[h*256];
        float s = 0.f;
        #pragma unroll 8
        for (int c = 0; c < 256; c++) s += qrow[c]*feats[c*65 + n];

        float gx = (sp[2*n]   + 1.f)*4.f;    // (x+1)/2*(W-1), W=9
        float gy = (sp[2*n+1] + 1.f)*4.f;
        float x0f = floorf(gx), y0f = floorf(gy);
        int   x0 = (int)x0f,    y0 = (int)y0f;
        float wx1 = gx - x0f, wx0 = 1.f - wx1;
        float wy1 = gy - y0f, wy0 = 1.f - wy1;
        const float* th = &tab[h*81];
        float bias = bil_corner(th, y0,   x0,   wy0*wx0)
                   + bil_corner(th, y0,   x0+1, wy0*wx1)
                   + bil_corner(th, y0+1, x0,   wy1*wx0)
                   + bil_corner(th, y0+1, x0+1, wy1*wx1);
        sc[p] = s + bias;
    }
    __syncthreads();

    // softmax over n per head: warp w handles head w
    {
        int w = tid >> 5, l = tid & 31;
        float v0 = sc[w*64 + l], v1 = sc[w*64 + 32 + l];
        float m = fmaxf(v0, v1);
        #pragma unroll
        for (int o = 16; o > 0; o >>= 1) m = fmaxf(m, __shfl_xor_sync(0xffffffffu, m, o));
        float e0 = expf(v0 - m), e1 = expf(v1 - m);
        float s = e0 + e1;
        #pragma unroll
        for (int o = 16; o > 0; o >>= 1) s += __shfl_xor_sync(0xffffffffu, s, o);
        float inv = 1.f/s;
        sc[w*64 + l]      = e0*inv;
        sc[w*64 + 32 + l] = e1*inv;
    }
    __syncthreads();

    // g[h][c=tid] = sum_n attn[h][n] * feats[tid][n]
    float acc[8] = {};
    #pragma unroll 4
    for (int n = 0; n < 64; n++) {
        float fv = feats[tid*65 + n];
        #pragma unroll
        for (int h = 0; h < 8; h++) acc[h] += sc[h*64 + n]*fv;
    }
    #pragma unroll
    for (int h = 0; h < 8; h++)
        gout[((size_t)bk*HEADS + h)*C_ + tid] = acc[h];
}

// ------- ctx[bk, h*32+d] = sum_c g[bk,h,c]*Wv[c,h*32+d] + bv[h*32+d] --------
// grid (NT/64, HEADS), 256 threads.
__global__ void ctx_kernel(const float* __restrict__ g, const float* __restrict__ Wv,
                           const float* __restrict__ bv, float* __restrict__ ctx)
{
    extern __shared__ float sm[];
    float* wvs = sm;            // [c][d] pad 33
    float* gs  = sm + 256*33;   // [r][c]
    const int tid = threadIdx.x;
    const int h = blockIdx.y, bk0 = blockIdx.x*64;

    #pragma unroll
    for (int j = 0; j < 32; j++) {
        int i = tid + 256*j;     // c*32+d
        int c = i >> 5, d = i & 31;
        wvs[c*33 + d] = Wv[c*C_ + h*DH + d];
    }
    #pragma unroll
    for (int j = 0; j < 16; j++) {
        int i = tid + 256*j;     // float4 index: r*64 + c4
        int r = i >> 6, c4 = i & 63;
        *(float4*)&gs[r*256 + c4*4] =
            *(const float4*)&g[((size_t)(bk0 + r)*HEADS + h)*C_ + c4*4];
    }
    __syncthreads();

    const int d = tid & 31, rg = tid >> 5;   // 8 row-groups
    float acc[8] = {};
    for (int c = 0; c < 256; c++) {
        float wv = wvs[c*33 + d];
        #pragma unroll
        for (int j = 0; j < 8; j++) acc[j] += gs[(rg*8 + j)*256 + c]*wv;
    }
    float bvv = bv[h*DH + d];
    #pragma unroll
    for (int j = 0; j < 8; j++)
        ctx[(size_t)(bk0 + rg*8 + j)*C_ + h*DH + d] = acc[j] + bvv;
}

// ---------------- LayerNorm over C=256 (one CTA per row) -------------------
__global__ void ln_kernel(const float* __restrict__ in, const float* __restrict__ gw,
                          const float* __restrict__ bw, float* __restrict__ out)
{
    const int row = blockIdx.x, t = threadIdx.x;
    float v = in[(size_t)row*C_ + t];
    float s = v, ss = v*v;
    #pragma unroll
    for (int o = 16; o > 0; o >>= 1) {
        s  += __shfl_xor_sync(0xffffffffu, s,  o);
        ss += __shfl_xor_sync(0xffffffffu, ss, o);
    }
    __shared__ float rs[8], rss[8];
    int w = t >> 5, l = t & 31;
    if (l == 0) { rs[w] = s; rss[w] = ss; }
    __syncthreads();
    if (w == 0) {
        float a  = (l < 8) ? rs[l]  : 0.f;
        float b2 = (l < 8) ? rss[l] : 0.f;
        #pragma unroll
        for (int o = 4; o > 0; o >>= 1) {
            a  += __shfl_xor_sync(0xffffffffu, a,  o);
            b2 += __shfl_xor_sync(0xffffffffu, b2, o);
        }
        if (l == 0) { rs[0] = a; rss[0] = b2; }
    }
    __syncthreads();
    float mu  = rs[0]*(1.f/C_);
    float var = rss[0]*(1.f/C_) - mu*mu;
    out[(size_t)row*C_ + t] = (v - mu)*rsqrtf(var + 1e-5f)*gw[t] + bw[t];
}

// ---------------------------------------------------------------------------
extern "C" void kernel_launch(void* const* d_in, const int* in_sizes, int n_in,
                              void* d_out, int out_size)
{
    const float* query = (const float*)d_in[0];
    const float* lf    = (const float*)d_in[1];
    const float* spat  = (const float*)d_in[2];
    const float* table = (const float*)d_in[3];
    const float* Wq    = (const float*)d_in[4];
    const float* bq    = (const float*)d_in[5];
    const float* Wk    = (const float*)d_in[6];
    // d_in[7] = bk: constant over n -> cancels in softmax, unused
    const float* Wv    = (const float*)d_in[8];
    const float* bv    = (const float*)d_in[9];
    const float* Wo    = (const float*)d_in[10];
    const float* bo    = (const float*)d_in[11];
    const float* ln1g  = (const float*)d_in[12];
    const float* ln1b  = (const float*)d_in[13];
    const float* W1    = (const float*)d_in[14];
    const float* b1    = (const float*)d_in[15];
    const float* W2    = (const float*)d_in[16];
    const float* b2    = (const float*)d_in[17];
    const float* ln2g  = (const float*)d_in[18];
    const float* ln2b  = (const float*)d_in[19];
    float* out = (float*)d_out;

    float *qp, *qkb, *gb, *ctxb, *yb, *xb, *h1b;
    cudaGetSymbolAddress((void**)&qp,   d_qp);
    cudaGetSymbolAddress((void**)&qkb,  d_qk);
    cudaGetSymbolAddress((void**)&gb,   d_g);
    cudaGetSymbolAddress((void**)&ctxb, d_ctx);
    cudaGetSymbolAddress((void**)&yb,   d_y);
    cudaGetSymbolAddress((void**)&xb,   d_x);
    cudaGetSymbolAddress((void**)&h1b,  d_h1);

    const int ATTN_SMEM = (256*65 + 2048 + 656 + 512 + 128) * (int)sizeof(float);
    const int CTX_SMEM  = (256*33 + 64*256) * (int)sizeof(float);
    cudaFuncSetAttribute(attn_kernel, cudaFuncAttributeMaxDynamicSharedMemorySize, ATTN_SMEM);
    cudaFuncSetAttribute(ctx_kernel,  cudaFuncAttributeMaxDynamicSharedMemorySize, CTX_SMEM);

    dim3 blk(256);

    // 1) qp = query @ Wq + bq
    gemm64<true,false,false><<<dim3(C_/64, NT/64), blk>>>(query, Wq, bq, nullptr, qp, NT, C_, C_);
    // 2) qk_coef (scaled)
    qk_kernel<<<dim3(NT/64, HEADS), blk>>>(qp, Wk, qkb);
    // 3) fused local attention -> g
    attn_kernel<<<NT, blk, ATTN_SMEM>>>(lf, spat, table, qkb, gb);
    // 4) ctx = g @ Wv_h + bv
    ctx_kernel<<<dim3(NT/64, HEADS), blk, CTX_SMEM>>>(gb, Wv, bv, ctxb);
    // 5) y = query + ctx @ Wo + bo
    gemm64<true,true,false><<<dim3(C_/64, NT/64), blk>>>(ctxb, Wo, bo, query, yb, NT, C_, C_);
    // 6) x = LN1(y)
    ln_kernel<<<NT, blk>>>(yb, ln1g, ln1b, xb);
    // 7) h1 = gelu(x @ W1 + b1)
    gemm64<true,false,true><<<dim3(FF_/64, NT/64), blk>>>(xb, W1, b1, nullptr, h1b, NT, FF_, C_);
    // 8) y = x + h1 @ W2 + b2
    gemm64<true,true,false><<<dim3(C_/64, NT/64), blk>>>(h1b, W2, b2, xb, yb, NT, C_, FF_);
    // 9) out = LN2(y)
    ln_kernel<<<NT, blk>>>(yb, ln2g, ln2b, out);
}

// round 3
// speedup vs baseline: 1.3300x; 1.3300x over previous
#include <cuda_runtime.h>
#include <cuda_bf16.h>
#include <math.h>
#include <cstdint>

// Problem constants
#define B_    8
#define KTOK  512
#define C_    256
#define HEADS 8
#define DH    32
#define NS    64
#define FF_   1024
#define NT    (B_*KTOK)   // 4096 tokens

// ---------------- scratch (device globals; no allocation allowed) ----------
__device__ float d_qp [NT*C_];
__device__ float d_qk [NT*HEADS*C_];
__device__ float d_g  [NT*HEADS*C_];
__device__ float d_ctx[NT*C_];
__device__ float d_y  [NT*C_];
__device__ float d_x  [NT*C_];
__device__ float d_h1 [NT*FF_];

__device__ __forceinline__ float gelu_tanh(float x) {
    float x3 = x*x*x;
    return 0.5f*x*(1.f + tanhf(0.7978845608028654f*(x + 0.044715f*x3)));
}

__device__ __forceinline__ uint32_t smem_u32(const void* p) {
    uint32_t a;
    asm("{ .reg .u64 t; cvta.to.shared.u64 t, %1; cvt.u32.u64 %0, t; }" : "=r"(a) : "l"(p));
    return a;
}

// ---- ldmatrix / mma.sync wrappers (arch-agnostic PTX, sm_80+) --------------
__device__ __forceinline__ void ldsm_x4(uint32_t (&r)[4], uint32_t addr) {
    asm volatile("ldmatrix.sync.aligned.m8n8.x4.shared.b16 {%0,%1,%2,%3}, [%4];"
        : "=r"(r[0]), "=r"(r[1]), "=r"(r[2]), "=r"(r[3]) : "r"(addr));
}
__device__ __forceinline__ void ldsm_x4_t(uint32_t (&r)[4], uint32_t addr) {
    asm volatile("ldmatrix.sync.aligned.m8n8.x4.trans.shared.b16 {%0,%1,%2,%3}, [%4];"
        : "=r"(r[0]), "=r"(r[1]), "=r"(r[2]), "=r"(r[3]) : "r"(addr));
}
__device__ __forceinline__ void mma_bf16(float (&d)[4], const uint32_t (&a)[4],
                                         uint32_t b0, uint32_t b1) {
    asm volatile(
        "mma.sync.aligned.m16n8k16.row.col.f32.bf16.bf16.f32 "
        "{%0,%1,%2,%3}, {%4,%5,%6,%7}, {%8,%9}, {%0,%1,%2,%3};"
        : "+f"(d[0]), "+f"(d[1]), "+f"(d[2]), "+f"(d[3])
        : "r"(a[0]), "r"(a[1]), "r"(a[2]), "r"(a[3]), "r"(b0), "r"(b1));
}

__device__ __forceinline__ void split2(float x, float y, uint32_t& h, uint32_t& l) {
    __nv_bfloat162 hh = __floats2bfloat162_rn(x, y);
    float rx = x - __bfloat162float(hh.x);
    float ry = y - __bfloat162float(hh.y);
    __nv_bfloat162 ll = __floats2bfloat162_rn(rx, ry);
    h = *(uint32_t*)&hh;  l = *(uint32_t*)&ll;
}

// ======= bf16 hi/lo split tensor-core GEMM: Out = f(A[M,K]@W[K,N]) ==========
// CTA: 128 x TN. 8 warps (4 m x 2 n), warp tile 32 x TN/2.
// K chunks of 32, double-buffered smem. D = Ah*Bh + Ah*Bl + Al*Bh (fp32 acc).
template<int TN, bool BIAS, bool RES, bool GELU>
__global__ __launch_bounds__(256)
void mma_gemm(const float* __restrict__ A, const float* __restrict__ W,
              const float* __restrict__ bias, const float* __restrict__ res,
              float* __restrict__ Out, int N, int K)
{
    constexpr int AROW   = 80;                 // 32 bf16 + 16B pad (odd chunk stride)
    constexpr int BROW   = TN*2 + 16;          // n-major row + pad
    constexpr int A_BYTES = 128*AROW;
    constexpr int B_BYTES = 32*BROW;
    constexpr int STAGE  = 2*A_BYTES + 2*B_BYTES;
    constexpr int NBJ    = (TN == 128) ? 4 : 2;  // B float4 loads / thread / chunk
    constexpr int NB16   = TN/32;                // n16 blocks per warp

    extern __shared__ char smem[];
    const int tid  = threadIdx.x;
    const int lane = tid & 31, wid = tid >> 5;
    const int wm = wid & 3, wn = wid >> 2;
    const int m0 = blockIdx.y*128, n0 = blockIdx.x*TN;

    float acc[2][NB16*2][4];
    #pragma unroll
    for (int a = 0; a < 2; a++)
        #pragma unroll
        for (int b = 0; b < NB16*2; b++)
            #pragma unroll
            for (int c = 0; c < 4; c++) acc[a][b][c] = 0.f;

    float4 av[4], bv[NBJ];

    auto gload = [&](int chunk) {
        const int kc = chunk*32;
        #pragma unroll
        for (int j = 0; j < 4; j++) {
            int idx = tid + 256*j, row = idx >> 3, kq = idx & 7;
            av[j] = *(const float4*)&A[(size_t)(m0 + row)*K + kc + kq*4];
        }
        #pragma unroll
        for (int j = 0; j < NBJ; j++) {
            int idx = tid + 256*j;
            int kr = (TN == 128) ? (idx >> 5) : (idx >> 4);
            int nq = (TN == 128) ? (idx & 31) : (idx & 15);
            bv[j] = *(const float4*)&W[(size_t)(kc + kr)*N + n0 + nq*4];
        }
    };
    auto sstore = [&](char* st) {
        char* Ah = st;             char* Al = st + A_BYTES;
        char* Bh = st + 2*A_BYTES; char* Bl = Bh + B_BYTES;
        #pragma unroll
        for (int j = 0; j < 4; j++) {
            int idx = tid + 256*j, row = idx >> 3, kq = idx & 7;
            uint32_t h0, l0, h1, l1;
            split2(av[j].x, av[j].y, h0, l0);
            split2(av[j].z, av[j].w, h1, l1);
            int off = row*AROW + kq*8;
            *(uint2*)(Ah + off) = make_uint2(h0, h1);
            *(uint2*)(Al + off) = make_uint2(l0, l1);
        }
        #pragma unroll
        for (int j = 0; j < NBJ; j++) {
            int idx = tid + 256*j;
            int kr = (TN == 128) ? (idx >> 5) : (idx >> 4);
            int nq = (TN == 128) ? (idx & 31) : (idx & 15);
            uint32_t h0, l0, h1, l1;
            split2(bv[j].x, bv[j].y, h0, l0);
            split2(bv[j].z, bv[j].w, h1, l1);
            int off = kr*BROW + nq*8;
            *(uint2*)(Bh + off) = make_uint2(h0, h1);
            *(uint2*)(Bl + off) = make_uint2(l0, l1);
        }
    };
    auto compute = [&](char* st) {
        const uint32_t a_h = smem_u32(st);
        const uint32_t a_l = a_h + A_BYTES;
        const uint32_t b_h = a_h + 2*A_BYTES;
        const uint32_t b_l = b_h + B_BYTES;
        const int l15 = lane & 15, l16 = lane >> 4;
        #pragma unroll
        for (int k16 = 0; k16 < 2; k16++) {
            uint32_t ah[2][4], al[2][4];
            #pragma unroll
            for (int mt = 0; mt < 2; mt++) {
                uint32_t aoff = (uint32_t)((wm*32 + mt*16 + l15)*AROW + k16*32 + l16*16);
                ldsm_x4(ah[mt], a_h + aoff);
                ldsm_x4(al[mt], a_l + aoff);
            }
            #pragma unroll
            for (int nb = 0; nb < NB16; nb++) {
                uint32_t boff = (uint32_t)((k16*16 + l15)*BROW + (wn*(TN/2) + nb*16)*2 + l16*16);
                uint32_t bh[4], bl[4];
                ldsm_x4_t(bh, b_h + boff);
                ldsm_x4_t(bl, b_l + boff);
                #pragma unroll
                for (int mt = 0; mt < 2; mt++) {
                    mma_bf16(acc[mt][nb*2],   ah[mt], bh[0], bh[1]);
                    mma_bf16(acc[mt][nb*2],   ah[mt], bl[0], bl[1]);
                    mma_bf16(acc[mt][nb*2],   al[mt], bh[0], bh[1]);
                    mma_bf16(acc[mt][nb*2+1], ah[mt], bh[2], bh[3]);
                    mma_bf16(acc[mt][nb*2+1], ah[mt], bl[2], bl[3]);
                    mma_bf16(acc[mt][nb*2+1], al[mt], bh[2], bh[3]);
                }
            }
        }
    };

    // ---- pipeline ----
    gload(0);
    sstore(smem);
    __syncthreads();
    const int NC = K/32;
    for (int i = 0; i < NC; i++) {
        if (i + 1 < NC) gload(i + 1);
        compute(smem + (size_t)(i & 1)*STAGE);
        if (i + 1 < NC) {
            sstore(smem + (size_t)((i + 1) & 1)*STAGE);
            __syncthreads();
        }
    }

    // ---- epilogue ----
    const int g = lane >> 2, tg = lane & 3;
    #pragma unroll
    for (int mt = 0; mt < 2; mt++) {
        const int r0 = m0 + wm*32 + mt*16 + g;
        #pragma unroll
        for (int j = 0; j < NB16*2; j++) {
            const int col = n0 + wn*(TN/2) + j*8 + tg*2;
            float v0 = acc[mt][j][0], v1 = acc[mt][j][1];
            float v2 = acc[mt][j][2], v3 = acc[mt][j][3];
            if (BIAS) {
                float b0 = bias[col], b1 = bias[col+1];
                v0 += b0; v1 += b1; v2 += b0; v3 += b1;
            }
            if (RES) {
                const float* rp0 = &res[(size_t)r0*N + col];
                const float* rp1 = &res[(size_t)(r0+8)*N + col];
                v0 += rp0[0]; v1 += rp0[1]; v2 += rp1[0]; v3 += rp1[1];
            }
            if (GELU) { v0 = gelu_tanh(v0); v1 = gelu_tanh(v1);
                        v2 = gelu_tanh(v2); v3 = gelu_tanh(v3); }
            *(float2*)&Out[(size_t)r0*N + col]     = make_float2(v0, v1);
            *(float2*)&Out[(size_t)(r0+8)*N + col] = make_float2(v2, v3);
        }
    }
}

// -------- qk_coef[bk,h,c] = (1/sqrt(32)) * sum_d qp[bk,h*32+d]*Wk[c,h*32+d] --
__global__ void qk_kernel(const float* __restrict__ qp, const float* __restrict__ Wk,
                          float* __restrict__ qk)
{
    __shared__ float wks[32*257];
    __shared__ float qps[64*33];
    const int tid = threadIdx.x;
    const int h   = blockIdx.y;
    const int bk0 = blockIdx.x * 64;

    #pragma unroll
    for (int j = 0; j < 32; j++) {
        int i = tid + 256*j;
        int c = i >> 5, d = i & 31;
        wks[d*257 + c] = Wk[c*C_ + h*DH + d];
    }
    #pragma unroll
    for (int j = 0; j < 8; j++) {
        int i = tid + 256*j;
        int r = i >> 5, d = i & 31;
        qps[r*33 + d] = qp[(size_t)(bk0 + r)*C_ + h*DH + d];
    }
    __syncthreads();

    float wreg[32];
    #pragma unroll
    for (int d = 0; d < 32; d++) wreg[d] = wks[d*257 + tid];

    const float scale = 0.17677669529663687f;
    for (int r = 0; r < 64; r++) {
        float acc = 0.f;
        #pragma unroll
        for (int d = 0; d < 32; d++) acc += qps[r*33 + d]*wreg[d];
        qk[((size_t)(bk0 + r)*HEADS + h)*C_ + tid] = acc*scale;
    }
}

// ---- bilinear tap of the 9x9 rel-pos table ---------------------------------
__device__ __forceinline__ float bil_corner(const float* __restrict__ th,
                                            int yi, int xi, float w)
{
    if (xi < 0 || xi > 8 || yi < 0 || yi > 8) return 0.f;
    return th[yi*9 + xi]*w;
}

// ---------------- fused local attention: one CTA per token -----------------
__global__ void attn_kernel(const float* __restrict__ lf,   const float* __restrict__ spat,
                            const float* __restrict__ table, const float* __restrict__ qk,
                            float* __restrict__ gout)
{
    extern __shared__ float sm[];
    float* feats = sm;                // [256][65]
    float* qks   = feats + 256*65;    // [8][256]
    float* tab   = qks + 2048;        // 648 (pad 656)
    float* sc    = tab + 656;         // [8][64]
    float* sp    = sc  + 512;         // [64][2]

    const int tid = threadIdx.x;
    const int bk  = blockIdx.x;
    const int b   = bk >> 9, k = bk & 511;

    {
        const float4* q4 = (const float4*)(qk + (size_t)bk*2048);
        float4* s4 = (float4*)qks;
        s4[tid]       = q4[tid];
        s4[tid + 256] = q4[tid + 256];
    }
    if (tid < 128) sp[tid] = spat[(size_t)bk*128 + tid];
    for (int j = tid; j < 648; j += 256) tab[j] = table[j];

    const float* lfb = lf + (size_t)b*(C_*KTOK*NS) + (size_t)k*NS;
    {
        const int v = tid & 15, cg = tid >> 4;
        #pragma unroll
        for (int rr = 0; rr < 16; rr++) {
            int c = rr*16 + cg;
            float4 f = *(const float4*)(lfb + (size_t)c*(KTOK*NS) + v*4);
            float* dst = &feats[c*65 + v*4];
            dst[0] = f.x; dst[1] = f.y; dst[2] = f.z; dst[3] = f.w;
        }
    }
    __syncthreads();

    #pragma unroll
    for (int pp = 0; pp < 2; pp++) {
        int p = tid + pp*256;
        int h = p >> 6, n = p & 63;
        const float* qrow = &qks[h*256];
        float s = 0.f;
        #pragma unroll 8
        for (int c = 0; c < 256; c++) s += qrow[c]*feats[c*65 + n];

        float gx = (sp[2*n]   + 1.f)*4.f;
        float gy = (sp[2*n+1] + 1.f)*4.f;
        float x0f = floorf(gx), y0f = floorf(gy);
        int   x0 = (int)x0f,    y0 = (int)y0f;
        float wx1 = gx - x0f, wx0 = 1.f - wx1;
        float wy1 = gy - y0f, wy0 = 1.f - wy1;
        const float* th = &tab[h*81];
        float bias = bil_corner(th, y0,   x0,   wy0*wx0)
                   + bil_corner(th, y0,   x0+1, wy0*wx1)
                   + bil_corner(th, y0+1, x0,   wy1*wx0)
                   + bil_corner(th, y0+1, x0+1, wy1*wx1);
        sc[p] = s + bias;
    }
    __syncthreads();

    {
        int w = tid >> 5, l = tid & 31;
        float v0 = sc[w*64 + l], v1 = sc[w*64 + 32 + l];
        float m = fmaxf(v0, v1);
        #pragma unroll
        for (int o = 16; o > 0; o >>= 1) m = fmaxf(m, __shfl_xor_sync(0xffffffffu, m, o));
        float e0 = expf(v0 - m), e1 = expf(v1 - m);
        float s = e0 + e1;
        #pragma unroll
        for (int o = 16; o > 0; o >>= 1) s += __shfl_xor_sync(0xffffffffu, s, o);
        float inv = 1.f/s;
        sc[w*64 + l]      = e0*inv;
        sc[w*64 + 32 + l] = e1*inv;
    }
    __syncthreads();

    float acc[8] = {};
    #pragma unroll 4
    for (int n = 0; n < 64; n++) {
        float fv = feats[tid*65 + n];
        #pragma unroll
        for (int h = 0; h < 8; h++) acc[h] += sc[h*64 + n]*fv;
    }
    #pragma unroll
    for (int h = 0; h < 8; h++)
        gout[((size_t)bk*HEADS + h)*C_ + tid] = acc[h];
}

// ------- ctx[bk, h*32+d] = sum_c g[bk,h,c]*Wv[c,h*32+d] + bv[h*32+d] --------
__global__ void ctx_kernel(const float* __restrict__ g, const float* __restrict__ Wv,
                           const float* __restrict__ bv, float* __restrict__ ctx)
{
    __shared__ float gs[64*68];
    __shared__ float wvs[64*33];
    const int tid = threadIdx.x;
    const int h = blockIdx.y, bk0 = blockIdx.x*64;
    const int d = tid & 31, rg = tid >> 5;
    float acc[8] = {};

    for (int kc = 0; kc < C_; kc += 64) {
        #pragma unroll
        for (int j = 0; j < 4; j++) {
            int idx = tid + 256*j;
            int r = idx >> 4, cq = idx & 15;
            float4 v = *(const float4*)&g[(((size_t)(bk0 + r)*HEADS) + h)*C_ + kc + cq*4];
            *(float4*)&gs[r*68 + cq*4] = v;
        }
        #pragma unroll
        for (int j = 0; j < 8; j++) {
            int idx = tid + 256*j;
            int c = idx >> 5, dd = idx & 31;
            wvs[c*33 + dd] = Wv[(size_t)(kc + c)*C_ + h*DH + dd];
        }
        __syncthreads();
        #pragma unroll 8
        for (int c = 0; c < 64; c++) {
            float w = wvs[c*33 + d];
            #pragma unroll
            for (int j = 0; j < 8; j++) acc[j] += gs[(rg*8 + j)*68 + c]*w;
        }
        __syncthreads();
    }
    float bvv = bv[h*DH + d];
    #pragma unroll
    for (int j = 0; j < 8; j++)
        ctx[(size_t)(bk0 + rg*8 + j)*C_ + h*DH + d] = acc[j] + bvv;
}

// ---------------- LayerNorm over C=256 (one CTA per row) -------------------
__global__ void ln_kernel(const float* __restrict__ in, const float* __restrict__ gw,
                          const float* __restrict__ bw, float* __restrict__ out)
{
    const int row = blockIdx.x, t = threadIdx.x;
    float v = in[(size_t)row*C_ + t];
    float s = v, ss = v*v;
    #pragma unroll
    for (int o = 16; o > 0; o >>= 1) {
        s  += __shfl_xor_sync(0xffffffffu, s,  o);
        ss += __shfl_xor_sync(0xffffffffu, ss, o);
    }
    __shared__ float rs[8], rss[8];
    int w = t >> 5, l = t & 31;
    if (l == 0) { rs[w] = s; rss[w] = ss; }
    __syncthreads();
    if (w == 0) {
        float a  = (l < 8) ? rs[l]  : 0.f;
        float b2 = (l < 8) ? rss[l] : 0.f;
        #pragma unroll
        for (int o = 4; o > 0; o >>= 1) {
            a  += __shfl_xor_sync(0xffffffffu, a,  o);
            b2 += __shfl_xor_sync(0xffffffffu, b2, o);
        }
        if (l == 0) { rs[0] = a; rss[0] = b2; }
    }
    __syncthreads();
    float mu  = rs[0]*(1.f/C_);
    float var = rss[0]*(1.f/C_) - mu*mu;
    out[(size_t)row*C_ + t] = (v - mu)*rsqrtf(var + 1e-5f)*gw[t] + bw[t];
}

// ---------------------------------------------------------------------------
extern "C" void kernel_launch(void* const* d_in, const int* in_sizes, int n_in,
                              void* d_out, int out_size)
{
    const float* query = (const float*)d_in[0];
    const float* lf    = (const float*)d_in[1];
    const float* spat  = (const float*)d_in[2];
    const float* table = (const float*)d_in[3];
    const float* Wq    = (const float*)d_in[4];
    const float* bq    = (const float*)d_in[5];
    const float* Wk    = (const float*)d_in[6];
    // d_in[7] = bk: constant over n -> cancels in softmax
    const float* Wv    = (const float*)d_in[8];
    const float* bv    = (const float*)d_in[9];
    const float* Wo    = (const float*)d_in[10];
    const float* bo    = (const float*)d_in[11];
    const float* ln1g  = (const float*)d_in[12];
    const float* ln1b  = (const float*)d_in[13];
    const float* W1    = (const float*)d_in[14];
    const float* b1    = (const float*)d_in[15];
    const float* W2    = (const float*)d_in[16];
    const float* b2    = (const float*)d_in[17];
    const float* ln2g  = (const float*)d_in[18];
    const float* ln2b  = (const float*)d_in[19];
    float* out = (float*)d_out;

    float *qp, *qkb, *gb, *ctxb, *yb, *xb, *h1b;
    cudaGetSymbolAddress((void**)&qp,   d_qp);
    cudaGetSymbolAddress((void**)&qkb,  d_qk);
    cudaGetSymbolAddress((void**)&gb,   d_g);
    cudaGetSymbolAddress((void**)&ctxb, d_ctx);
    cudaGetSymbolAddress((void**)&yb,   d_y);
    cudaGetSymbolAddress((void**)&xb,   d_x);
    cudaGetSymbolAddress((void**)&h1b,  d_h1);

    const int ATTN_SMEM = (256*65 + 2048 + 656 + 512 + 128) * (int)sizeof(float);
    cudaFuncSetAttribute(attn_kernel, cudaFuncAttributeMaxDynamicSharedMemorySize, ATTN_SMEM);

    // mma_gemm dynamic smem: 2 stages of (2*A + 2*B)
    const int SM64  = 2*(2*128*80 + 2*32*(64*2 + 16));    // 59392
    const int SM128 = 2*(2*128*80 + 2*32*(128*2 + 16));   // 75776
    cudaFuncSetAttribute((const void*)mma_gemm<64,true,false,false>, cudaFuncAttributeMaxDynamicSharedMemorySize, SM64);
    cudaFuncSetAttribute((const void*)mma_gemm<64,true,true,false>,  cudaFuncAttributeMaxDynamicSharedMemorySize, SM64);
    cudaFuncSetAttribute((const void*)mma_gemm<128,true,false,true>, cudaFuncAttributeMaxDynamicSharedMemorySize, SM128);

    dim3 blk(256);

    // 1) qp = query @ Wq + bq
    mma_gemm<64,true,false,false><<<dim3(C_/64, NT/128), blk, SM64>>>(query, Wq, bq, nullptr, qp, C_, C_);
    // 2) qk_coef (scaled)
    qk_kernel<<<dim3(NT/64, HEADS), blk>>>(qp, Wk, qkb);
    // 3) fused local attention -> g
    attn_kernel<<<NT, blk, ATTN_SMEM>>>(lf, spat, table, qkb, gb);
    // 4) ctx = g @ Wv_h + bv
    ctx_kernel<<<dim3(NT/64, HEADS), blk>>>(gb, Wv, bv, ctxb);
    // 5) y = query + ctx @ Wo + bo
    mma_gemm<64,true,true,false><<<dim3(C_/64, NT/128), blk, SM64>>>(ctxb, Wo, bo, query, yb, C_, C_);
    // 6) x = LN1(y)
    ln_kernel<<<NT, blk>>>(yb, ln1g, ln1b, xb);
    // 7) h1 = gelu(x @ W1 + b1)
    mma_gemm<128,true,false,true><<<dim3(FF_/128, NT/128), blk, SM128>>>(xb, W1, b1, nullptr, h1b, FF_, C_);
    // 8) y = x + h1 @ W2 + b2
    mma_gemm<64,true,true,false><<<dim3(C_/64, NT/128), blk, SM64>>>(h1b, W2, b2, xb, yb, C_, FF_);
    // 9) out = LN2(y)
    ln_kernel<<<NT, blk>>>(yb, ln2g, ln2b, out);
}

// round 4
// speedup vs baseline: 1.7720x; 1.3324x over previous
#include <cuda_runtime.h>
#include <cuda_bf16.h>
#include <math.h>
#include <cstdint>

// Problem constants
#define B_    8
#define KTOK  512
#define C_    256
#define HEADS 8
#define DH    32
#define NS    64
#define FF_   1024
#define NT    (B_*KTOK)   // 4096 tokens

// ---------------- scratch (device globals; no allocation allowed) ----------
__device__ float d_qp [NT*C_];
__device__ float d_qk [NT*HEADS*C_];
__device__ float d_g  [NT*HEADS*C_];
__device__ float d_ctx[NT*C_];
__device__ float d_y  [NT*C_];
__device__ float d_x  [NT*C_];
__device__ float d_h1 [NT*FF_];

__device__ __forceinline__ float gelu_tanh(float x) {
    float x3 = x*x*x;
    return 0.5f*x*(1.f + tanhf(0.7978845608028654f*(x + 0.044715f*x3)));
}

__device__ __forceinline__ uint32_t smem_u32(const void* p) {
    uint32_t a;
    asm("{ .reg .u64 t; cvta.to.shared.u64 t, %1; cvt.u32.u64 %0, t; }" : "=r"(a) : "l"(p));
    return a;
}

// ---- ldmatrix / mma.sync wrappers (arch-agnostic PTX, sm_80+) --------------
__device__ __forceinline__ void ldsm_x4(uint32_t (&r)[4], uint32_t addr) {
    asm volatile("ldmatrix.sync.aligned.m8n8.x4.shared.b16 {%0,%1,%2,%3}, [%4];"
        : "=r"(r[0]), "=r"(r[1]), "=r"(r[2]), "=r"(r[3]) : "r"(addr));
}
__device__ __forceinline__ void ldsm_x4_t(uint32_t (&r)[4], uint32_t addr) {
    asm volatile("ldmatrix.sync.aligned.m8n8.x4.trans.shared.b16 {%0,%1,%2,%3}, [%4];"
        : "=r"(r[0]), "=r"(r[1]), "=r"(r[2]), "=r"(r[3]) : "r"(addr));
}
__device__ __forceinline__ void ldsm_x2(uint32_t (&r)[2], uint32_t addr) {
    asm volatile("ldmatrix.sync.aligned.m8n8.x2.shared.b16 {%0,%1}, [%2];"
        : "=r"(r[0]), "=r"(r[1]) : "r"(addr));
}
__device__ __forceinline__ void ldsm_x2_t(uint32_t (&r)[2], uint32_t addr) {
    asm volatile("ldmatrix.sync.aligned.m8n8.x2.trans.shared.b16 {%0,%1}, [%2];"
        : "=r"(r[0]), "=r"(r[1]) : "r"(addr));
}
__device__ __forceinline__ void mma_bf16(float (&d)[4], const uint32_t (&a)[4],
                                         uint32_t b0, uint32_t b1) {
    asm volatile(
        "mma.sync.aligned.m16n8k16.row.col.f32.bf16.bf16.f32 "
        "{%0,%1,%2,%3}, {%4,%5,%6,%7}, {%8,%9}, {%0,%1,%2,%3};"
        : "+f"(d[0]), "+f"(d[1]), "+f"(d[2]), "+f"(d[3])
        : "r"(a[0]), "r"(a[1]), "r"(a[2]), "r"(a[3]), "r"(b0), "r"(b1));
}

__device__ __forceinline__ void split2(float x, float y, uint32_t& h, uint32_t& l) {
    __nv_bfloat162 hh = __floats2bfloat162_rn(x, y);
    float rx = x - __bfloat162float(hh.x);
    float ry = y - __bfloat162float(hh.y);
    __nv_bfloat162 ll = __floats2bfloat162_rn(rx, ry);
    h = *(uint32_t*)&hh;  l = *(uint32_t*)&ll;
}

// ======= bf16 hi/lo split tensor-core GEMM (strided, z-batched) =============
// CTA: 128 x TN. 8 warps (4 m x 2 n). K chunks of 32, double-buffered smem.
// D = Ah*Bh + Ah*Bl + Al*Bh (fp32 acc).
template<int TN, bool BIAS, bool RES, bool GELU>
__global__ __launch_bounds__(256)
void mma_gemm(const float* __restrict__ A, int lda,
              const float* __restrict__ W, int ldw,
              const float* __restrict__ bias, const float* __restrict__ res,
              float* __restrict__ Out, int ldo, int K,
              int za, int zw, int zb, int zo)
{
    constexpr int AROW   = 80;
    constexpr int BROW   = TN*2 + 16;
    constexpr int A_BYTES = 128*AROW;
    constexpr int B_BYTES = 32*BROW;
    constexpr int STAGE  = 2*A_BYTES + 2*B_BYTES;
    constexpr int NBJ    = TN/32;
    constexpr int QPR    = TN/4;
    constexpr int NB16   = TN/32;

    extern __shared__ char smem[];
    const int tid  = threadIdx.x;
    const int lane = tid & 31, wid = tid >> 5;
    const int wm = wid & 3, wn = wid >> 2;
    const int m0 = blockIdx.y*128, n0 = blockIdx.x*TN;
    const int z = blockIdx.z;
    A += (size_t)z*za;  W += (size_t)z*zw;
    Out += (size_t)z*zo;
    if (BIAS) bias += (size_t)z*zb;
    if (RES)  res  += (size_t)z*zo;

    float acc[2][NB16*2][4];
    #pragma unroll
    for (int a = 0; a < 2; a++)
        #pragma unroll
        for (int b = 0; b < NB16*2; b++)
            #pragma unroll
            for (int c = 0; c < 4; c++) acc[a][b][c] = 0.f;

    float4 av[4], bv[NBJ];

    auto gload = [&](int chunk) {
        const int kc = chunk*32;
        #pragma unroll
        for (int j = 0; j < 4; j++) {
            int idx = tid + 256*j, row = idx >> 3, kq = idx & 7;
            av[j] = *(const float4*)&A[(size_t)(m0 + row)*lda + kc + kq*4];
        }
        #pragma unroll
        for (int j = 0; j < NBJ; j++) {
            int idx = tid + 256*j;
            int kr = idx / QPR, nq = idx % QPR;
            bv[j] = *(const float4*)&W[(size_t)(kc + kr)*ldw + n0 + nq*4];
        }
    };
    auto sstore = [&](char* st) {
        char* Ah = st;             char* Al = st + A_BYTES;
        char* Bh = st + 2*A_BYTES; char* Bl = Bh + B_BYTES;
        #pragma unroll
        for (int j = 0; j < 4; j++) {
            int idx = tid + 256*j, row = idx >> 3, kq = idx & 7;
            uint32_t h0, l0, h1, l1;
            split2(av[j].x, av[j].y, h0, l0);
            split2(av[j].z, av[j].w, h1, l1);
            int off = row*AROW + kq*8;
            *(uint2*)(Ah + off) = make_uint2(h0, h1);
            *(uint2*)(Al + off) = make_uint2(l0, l1);
        }
        #pragma unroll
        for (int j = 0; j < NBJ; j++) {
            int idx = tid + 256*j;
            int kr = idx / QPR, nq = idx % QPR;
            uint32_t h0, l0, h1, l1;
            split2(bv[j].x, bv[j].y, h0, l0);
            split2(bv[j].z, bv[j].w, h1, l1);
            int off = kr*BROW + nq*8;
            *(uint2*)(Bh + off) = make_uint2(h0, h1);
            *(uint2*)(Bl + off) = make_uint2(l0, l1);
        }
    };
    auto compute = [&](char* st) {
        const uint32_t a_h = smem_u32(st);
        const uint32_t a_l = a_h + A_BYTES;
        const uint32_t b_h = a_h + 2*A_BYTES;
        const uint32_t b_l = b_h + B_BYTES;
        const int l15 = lane & 15, l16 = lane >> 4;
        #pragma unroll
        for (int k16 = 0; k16 < 2; k16++) {
            uint32_t ah[2][4], al[2][4];
            #pragma unroll
            for (int mt = 0; mt < 2; mt++) {
                uint32_t aoff = (uint32_t)((wm*32 + mt*16 + l15)*AROW + k16*32 + l16*16);
                ldsm_x4(ah[mt], a_h + aoff);
                ldsm_x4(al[mt], a_l + aoff);
            }
            #pragma unroll
            for (int nb = 0; nb < NB16; nb++) {
                uint32_t boff = (uint32_t)((k16*16 + l15)*BROW + (wn*(TN/2) + nb*16)*2 + l16*16);
                uint32_t bh[4], bl[4];
                ldsm_x4_t(bh, b_h + boff);
                ldsm_x4_t(bl, b_l + boff);
                #pragma unroll
                for (int mt = 0; mt < 2; mt++) {
                    mma_bf16(acc[mt][nb*2],   ah[mt], bh[0], bh[1]);
                    mma_bf16(acc[mt][nb*2],   ah[mt], bl[0], bl[1]);
                    mma_bf16(acc[mt][nb*2],   al[mt], bh[0], bh[1]);
                    mma_bf16(acc[mt][nb*2+1], ah[mt], bh[2], bh[3]);
                    mma_bf16(acc[mt][nb*2+1], ah[mt], bl[2], bl[3]);
                    mma_bf16(acc[mt][nb*2+1], al[mt], bh[2], bh[3]);
                }
            }
        }
    };

    gload(0);
    sstore(smem);
    __syncthreads();
    const int NC = K/32;
    for (int i = 0; i < NC; i++) {
        if (i + 1 < NC) gload(i + 1);
        compute(smem + (size_t)(i & 1)*STAGE);
        if (i + 1 < NC) {
            sstore(smem + (size_t)((i + 1) & 1)*STAGE);
            __syncthreads();
        }
    }

    const int g = lane >> 2, tg = lane & 3;
    #pragma unroll
    for (int mt = 0; mt < 2; mt++) {
        const int r0 = m0 + wm*32 + mt*16 + g;
        #pragma unroll
        for (int j = 0; j < NB16*2; j++) {
            const int col = n0 + wn*(TN/2) + j*8 + tg*2;
            float v0 = acc[mt][j][0], v1 = acc[mt][j][1];
            float v2 = acc[mt][j][2], v3 = acc[mt][j][3];
            if (BIAS) {
                float b0 = bias[col], b1 = bias[col+1];
                v0 += b0; v1 += b1; v2 += b0; v3 += b1;
            }
            if (RES) {
                const float* rp0 = &res[(size_t)r0*ldo + col];
                const float* rp1 = &res[(size_t)(r0+8)*ldo + col];
                v0 += rp0[0]; v1 += rp0[1]; v2 += rp1[0]; v3 += rp1[1];
            }
            if (GELU) { v0 = gelu_tanh(v0); v1 = gelu_tanh(v1);
                        v2 = gelu_tanh(v2); v3 = gelu_tanh(v3); }
            *(float2*)&Out[(size_t)r0*ldo + col]     = make_float2(v0, v1);
            *(float2*)&Out[(size_t)(r0+8)*ldo + col] = make_float2(v2, v3);
        }
    }
}

// -------- qk_coef[bk,h,c] = (1/sqrt(32)) * sum_d qp[bk,h*32+d]*Wk[c,h*32+d] --
__global__ void qk_kernel(const float* __restrict__ qp, const float* __restrict__ Wk,
                          float* __restrict__ qk)
{
    __shared__ float wks[32*257];
    __shared__ float qps[64*33];
    const int tid = threadIdx.x;
    const int h   = blockIdx.y;
    const int bk0 = blockIdx.x * 64;

    #pragma unroll
    for (int j = 0; j < 32; j++) {
        int i = tid + 256*j;
        int c = i >> 5, d = i & 31;
        wks[d*257 + c] = Wk[c*C_ + h*DH + d];
    }
    #pragma unroll
    for (int j = 0; j < 8; j++) {
        int i = tid + 256*j;
        int r = i >> 5, d = i & 31;
        qps[r*33 + d] = qp[(size_t)(bk0 + r)*C_ + h*DH + d];
    }
    __syncthreads();

    float wreg[32];
    #pragma unroll
    for (int d = 0; d < 32; d++) wreg[d] = wks[d*257 + tid];

    const float scale = 0.17677669529663687f;
    for (int r = 0; r < 64; r++) {
        float acc = 0.f;
        #pragma unroll
        for (int d = 0; d < 32; d++) acc += qps[r*33 + d]*wreg[d];
        qk[((size_t)(bk0 + r)*HEADS + h)*C_ + tid] = acc*scale;
    }
}

// ---- bilinear tap of the 9x9 rel-pos table ---------------------------------
__device__ __forceinline__ float bil_corner(const float* __restrict__ th,
                                            int yi, int xi, float w)
{
    if (xi < 0 || xi > 8 || yi < 0 || yi > 8) return 0.f;
    return th[yi*9 + xi]*w;
}

__device__ __forceinline__ float grid_bias(const float* __restrict__ sp,
                                           const float* __restrict__ tab,
                                           int h, int n)
{
    float gx = (sp[2*n]   + 1.f)*4.f;
    float gy = (sp[2*n+1] + 1.f)*4.f;
    float x0f = floorf(gx), y0f = floorf(gy);
    int   x0 = (int)x0f,    y0 = (int)y0f;
    float wx1 = gx - x0f, wx0 = 1.f - wx1;
    float wy1 = gy - y0f, wy0 = 1.f - wy1;
    const float* th = &tab[h*81];
    return bil_corner(th, y0,   x0,   wy0*wx0)
         + bil_corner(th, y0,   x0+1, wy0*wx1)
         + bil_corner(th, y0+1, x0,   wy1*wx0)
         + bil_corner(th, y0+1, x0+1, wy1*wx1);
}

// ---------------- fused local attention (tensor-core), one CTA per token ----
// smem layout (bytes):
//   FH  = 0       feats hi bf16 [256][64], pitch 144   -> 36864
//   FL  = 36864   feats lo                              -> 73728
//   QH  = 73728   qk hi bf16 [16][256], pitch 528       -> 82176
//   QL  = 82176                                         -> 90624
//   PH  = 90624   probs hi bf16 [16][64], pitch 144     -> 92928
//   PL  = 92928                                         -> 95232
//   SC  = 95232   scores/probs fp32 [8][64]             -> 97280
//   SP  = 97280   spat fp32 [128]                       -> 97792
//   TAB = 97792   table fp32 [656]                      -> 100416
#define ASM_FH  0
#define ASM_FL  36864
#define ASM_QH  73728
#define ASM_QL  82176
#define ASM_PH  90624
#define ASM_PL  92928
#define ASM_SC  95232
#define ASM_SP  97280
#define ASM_TAB 97792
#define ATTN_SMEM_BYTES 100416
#define FPITCH 144
#define QPITCH 528

__global__ __launch_bounds__(256)
void attn_kernel(const float* __restrict__ lf,   const float* __restrict__ spat,
                 const float* __restrict__ table, const float* __restrict__ qk,
                 float* __restrict__ gout)
{
    extern __shared__ char smem[];
    float* sc  = (float*)(smem + ASM_SC);
    float* sp  = (float*)(smem + ASM_SP);
    float* tab = (float*)(smem + ASM_TAB);
    const uint32_t sb  = smem_u32(smem);
    const uint32_t sFH = sb + ASM_FH, sFL = sb + ASM_FL;
    const uint32_t sQH = sb + ASM_QH, sQL = sb + ASM_QL;
    const uint32_t sPH = sb + ASM_PH, sPL = sb + ASM_PL;

    const int tid  = threadIdx.x;
    const int lane = tid & 31, w = tid >> 5;
    const int bk = blockIdx.x;
    const int b  = bk >> 9, k = bk & 511;

    // ---- phase 0: load + split -------------------------------------------
    // qk row -> QH/QL (bf16 hi/lo, rows 0..7; rows 8..15 left garbage)
    {
        const float4* q4 = (const float4*)(qk + (size_t)bk*2048);
        #pragma unroll
        for (int j = 0; j < 2; j++) {
            int i4 = tid + 256*j;
            float4 v = q4[i4];
            int h = i4 >> 6, cq = (i4 & 63)*4;
            uint32_t h0, l0, h1, l1;
            split2(v.x, v.y, h0, l0);
            split2(v.z, v.w, h1, l1);
            uint32_t off = h*QPITCH + cq*2;
            *(uint2*)(smem + ASM_QH + off) = make_uint2(h0, h1);
            *(uint2*)(smem + ASM_QL + off) = make_uint2(l0, l1);
        }
    }
    if (tid < 128) sp[tid] = spat[(size_t)bk*128 + tid];
    for (int j = tid; j < 648; j += 256) tab[j] = table[j];

    // feats[c][n] bf16 hi/lo
    {
        const float* lfb = lf + (size_t)b*(C_*KTOK*NS) + (size_t)k*NS;
        const int v = tid & 15, cg = tid >> 4;
        #pragma unroll
        for (int rr = 0; rr < 16; rr++) {
            int c = rr*16 + cg;
            float4 f = *(const float4*)(lfb + (size_t)c*(KTOK*NS) + v*4);
            uint32_t h0, l0, h1, l1;
            split2(f.x, f.y, h0, l0);
            split2(f.z, f.w, h1, l1);
            uint32_t off = c*FPITCH + v*8;
            *(uint2*)(smem + ASM_FH + off) = make_uint2(h0, h1);
            *(uint2*)(smem + ASM_FL + off) = make_uint2(l0, l1);
        }
    }
    __syncthreads();

    // ---- phase 1: scores = qk @ feats (warp w owns n8 block n0 = 8w) ------
    {
        float d[4] = {0.f, 0.f, 0.f, 0.f};
        const int l15 = lane & 15;
        #pragma unroll
        for (int k16 = 0; k16 < 16; k16++) {
            uint32_t ah[4], al[4];
            uint32_t aaddr = sQH + (uint32_t)(l15*QPITCH + k16*32 + (lane>>4)*16);
            ldsm_x4(ah, aaddr);
            ldsm_x4(al, aaddr + (ASM_QL - ASM_QH));
            uint32_t bh[2], bl[2];
            uint32_t baddr = sFH + (uint32_t)((k16*16 + l15)*FPITCH + w*16);
            ldsm_x2_t(bh, baddr);
            ldsm_x2_t(bl, baddr + (ASM_FL - ASM_FH));
            mma_bf16(d, ah, bh[0], bh[1]);
            mma_bf16(d, ah, bl[0], bl[1]);
            mma_bf16(d, al, bh[0], bh[1]);
        }
        int h = lane >> 2;
        int n = w*8 + 2*(lane & 3);
        float b0 = grid_bias(sp, tab, h, n);
        float b1 = grid_bias(sp, tab, h, n + 1);
        *(float2*)&sc[h*64 + n] = make_float2(d[0] + b0, d[1] + b1);
    }
    __syncthreads();

    // ---- softmax over n per head (warp w = head w) -------------------------
    {
        float v0 = sc[w*64 + lane], v1 = sc[w*64 + 32 + lane];
        float m = fmaxf(v0, v1);
        #pragma unroll
        for (int o = 16; o > 0; o >>= 1) m = fmaxf(m, __shfl_xor_sync(0xffffffffu, m, o));
        float e0 = expf(v0 - m), e1 = expf(v1 - m);
        float s = e0 + e1;
        #pragma unroll
        for (int o = 16; o > 0; o >>= 1) s += __shfl_xor_sync(0xffffffffu, s, o);
        float inv = 1.f/s;
        sc[w*64 + lane]      = e0*inv;
        sc[w*64 + 32 + lane] = e1*inv;
    }
    __syncthreads();

    // ---- convert probs to bf16 hi/lo (rows 0..7; 8..15 garbage) -----------
    {
        int i = tid*2;
        int h = i >> 6, n = i & 63;
        float2 p = *(const float2*)&sc[h*64 + n];
        uint32_t ph, pl;
        split2(p.x, p.y, ph, pl);
        uint32_t off = h*FPITCH + n*2;
        *(uint32_t*)(smem + ASM_PH + off) = ph;
        *(uint32_t*)(smem + ASM_PL + off) = pl;
    }
    __syncthreads();

    // ---- phase 2: g = P @ feats^T (warp w owns c block 32w) ----------------
    {
        float dacc[4][4];
        #pragma unroll
        for (int i = 0; i < 4; i++)
            #pragma unroll
            for (int j = 0; j < 4; j++) dacc[i][j] = 0.f;
        const int l15 = lane & 15;
        #pragma unroll
        for (int k16 = 0; k16 < 4; k16++) {
            uint32_t ah[4], al[4];
            uint32_t aaddr = sPH + (uint32_t)(l15*FPITCH + k16*32 + (lane>>4)*16);
            ldsm_x4(ah, aaddr);
            ldsm_x4(al, aaddr + (ASM_PL - ASM_PH));
            #pragma unroll
            for (int blk = 0; blk < 4; blk++) {
                int crow = w*32 + blk*8;
                uint32_t baddr = sFH + (uint32_t)((crow + (lane & 7))*FPITCH
                                                  + k16*32 + ((lane>>3)&1)*16);
                uint32_t bh[2], bl[2];
                ldsm_x2(bh, baddr);
                ldsm_x2(bl, baddr + (ASM_FL - ASM_FH));
                mma_bf16(dacc[blk], ah, bh[0], bh[1]);
                mma_bf16(dacc[blk], ah, bl[0], bl[1]);
                mma_bf16(dacc[blk], al, bh[0], bh[1]);
            }
        }
        int h = lane >> 2;
        float* gdst = gout + ((size_t)bk*HEADS + h)*C_;
        #pragma unroll
        for (int blk = 0; blk < 4; blk++) {
            int c = w*32 + blk*8 + 2*(lane & 3);
            *(float2*)&gdst[c] = make_float2(dacc[blk][0], dacc[blk][1]);
        }
    }
}

// ---------------- LayerNorm over C=256 (one CTA per row) -------------------
__global__ void ln_kernel(const float* __restrict__ in, const float* __restrict__ gw,
                          const float* __restrict__ bw, float* __restrict__ out)
{
    const int row = blockIdx.x, t = threadIdx.x;
    float v = in[(size_t)row*C_ + t];
    float s = v, ss = v*v;
    #pragma unroll
    for (int o = 16; o > 0; o >>= 1) {
        s  += __shfl_xor_sync(0xffffffffu, s,  o);
        ss += __shfl_xor_sync(0xffffffffu, ss, o);
    }
    __shared__ float rs[8], rss[8];
    int w = t >> 5, l = t & 31;
    if (l == 0) { rs[w] = s; rss[w] = ss; }
    __syncthreads();
    if (w == 0) {
        float a  = (l < 8) ? rs[l]  : 0.f;
        float b2 = (l < 8) ? rss[l] : 0.f;
        #pragma unroll
        for (int o = 4; o > 0; o >>= 1) {
            a  += __shfl_xor_sync(0xffffffffu, a,  o);
            b2 += __shfl_xor_sync(0xffffffffu, b2, o);
        }
        if (l == 0) { rs[0] = a; rss[0] = b2; }
    }
    __syncthreads();
    float mu  = rs[0]*(1.f/C_);
    float var = rss[0]*(1.f/C_) - mu*mu;
    out[(size_t)row*C_ + t] = (v - mu)*rsqrtf(var + 1e-5f)*gw[t] + bw[t];
}

// ---------------------------------------------------------------------------
extern "C" void kernel_launch(void* const* d_in, const int* in_sizes, int n_in,
                              void* d_out, int out_size)
{
    const float* query = (const float*)d_in[0];
    const float* lf    = (const float*)d_in[1];
    const float* spat  = (const float*)d_in[2];
    const float* table = (const float*)d_in[3];
    const float* Wq    = (const float*)d_in[4];
    const float* bq    = (const float*)d_in[5];
    const float* Wk    = (const float*)d_in[6];
    // d_in[7] = bk: constant over n -> cancels in softmax
    const float* Wv    = (const float*)d_in[8];
    const float* bv    = (const float*)d_in[9];
    const float* Wo    = (const float*)d_in[10];
    const float* bo    = (const float*)d_in[11];
    const float* ln1g  = (const float*)d_in[12];
    const float* ln1b  = (const float*)d_in[13];
    const float* W1    = (const float*)d_in[14];
    const float* b1    = (const float*)d_in[15];
    const float* W2    = (const float*)d_in[16];
    const float* b2    = (const float*)d_in[17];
    const float* ln2g  = (const float*)d_in[18];
    const float* ln2b  = (const float*)d_in[19];
    float* out = (float*)d_out;

    float *qp, *qkb, *gb, *ctxb, *yb, *xb, *h1b;
    cudaGetSymbolAddress((void**)&qp,   d_qp);
    cudaGetSymbolAddress((void**)&qkb,  d_qk);
    cudaGetSymbolAddress((void**)&gb,   d_g);
    cudaGetSymbolAddress((void**)&ctxb, d_ctx);
    cudaGetSymbolAddress((void**)&yb,   d_y);
    cudaGetSymbolAddress((void**)&xb,   d_x);
    cudaGetSymbolAddress((void**)&h1b,  d_h1);

    cudaFuncSetAttribute(attn_kernel, cudaFuncAttributeMaxDynamicSharedMemorySize,
                         ATTN_SMEM_BYTES);

    const int SM32  = 2*(2*128*80 + 2*32*(32*2 + 16));    // 51200
    const int SM64  = 2*(2*128*80 + 2*32*(64*2 + 16));    // 59392
    const int SM128 = 2*(2*128*80 + 2*32*(128*2 + 16));   // 75776
    cudaFuncSetAttribute((const void*)mma_gemm<32,true,false,false>,  cudaFuncAttributeMaxDynamicSharedMemorySize, SM32);
    cudaFuncSetAttribute((const void*)mma_gemm<64,true,false,false>,  cudaFuncAttributeMaxDynamicSharedMemorySize, SM64);
    cudaFuncSetAttribute((const void*)mma_gemm<64,true,true,false>,   cudaFuncAttributeMaxDynamicSharedMemorySize, SM64);
    cudaFuncSetAttribute((const void*)mma_gemm<128,true,false,true>,  cudaFuncAttributeMaxDynamicSharedMemorySize, SM128);

    dim3 blk(256);

    // 1) qp = query @ Wq + bq
    mma_gemm<64,true,false,false><<<dim3(C_/64, NT/128, 1), blk, SM64>>>(
        query, C_, Wq, C_, bq, nullptr, qp, C_, C_, 0, 0, 0, 0);
    // 2) qk_coef (scaled)
    qk_kernel<<<dim3(NT/64, HEADS), blk>>>(qp, Wk, qkb);
    // 3) fused local attention (tensor core) -> g
    attn_kernel<<<NT, blk, ATTN_SMEM_BYTES>>>(lf, spat, table, qkb, gb);
    // 4) ctx = g @ Wv_h + bv   (8 head-batched GEMMs via grid.z)
    mma_gemm<32,true,false,false><<<dim3(1, NT/128, HEADS), blk, SM32>>>(
        gb, HEADS*C_, Wv, C_, bv, nullptr, ctxb, C_, C_,
        /*za=*/C_, /*zw=*/DH, /*zb=*/DH, /*zo=*/DH);
    // 5) y = query + ctx @ Wo + bo
    mma_gemm<64,true,true,false><<<dim3(C_/64, NT/128, 1), blk, SM64>>>(
        ctxb, C_, Wo, C_, bo, query, yb, C_, C_, 0, 0, 0, 0);
    // 6) x = LN1(y)
    ln_kernel<<<NT, blk>>>(yb, ln1g, ln1b, xb);
    // 7) h1 = gelu(x @ W1 + b1)
    mma_gemm<128,true,false,true><<<dim3(FF_/128, NT/128, 1), blk, SM128>>>(
        xb, C_, W1, FF_, b1, nullptr, h1b, FF_, C_, 0, 0, 0, 0);
    // 8) y = x + h1 @ W2 + b2
    mma_gemm<64,true,true,false><<<dim3(C_/64, NT/128, 1), blk, SM64>>>(
        h1b, FF_, W2, C_, b2, xb, yb, C_, FF_, 0, 0, 0, 0);
    // 9) out = LN2(y)
    ln_kernel<<<NT, blk>>>(yb, ln2g, ln2b, out);
}